// round 3
// baseline (speedup 1.0000x reference)
#include <cuda_runtime.h>
#include <cuda_bf16.h>

// Resample2d bilinear warp, smem-staged gather.
// input1: [B=8, D=64, H=384, W=512] fp32 ; input2: [B=8, 2, H, W] flow ;
// out NCHW fp32.
//
// R2 profile: L1tex 82.8% (binding), DRAM 47%, occ 93%. Gathers scatter over
// ~5 rows/warp -> ~7.7 wavefronts per gather LDG, 4 gathers re-touch the same
// lines. Fix: per (block, channel) stage the bounding tile (<=8 rows x 264
// cols) into smem once with coalesced float4 loads; gather via LDS. Lanes
// whose (y0,x0) falls outside the tile (|flow| > ~3, ~0.3%) use the original
// global-gather path (identical arithmetic).

#define B_ 8
#define D_ 64
#define H_ 384
#define W_ 512
#define PLANE_ (H_ * W_)
#define TPB 256
#define M_ 3                      // stage margin
#define NROWS_MAX (2 * M_ + 2)    // 8
#define STRIDE_ 268               // floats per tile row (mult of 4, 16B-aligned, bank-scrambling)

__global__ __launch_bounds__(TPB)
void resample2d_kernel(const float* __restrict__ img,
                       const float* __restrict__ flow,
                       float* __restrict__ out)
{
    __shared__ float tile0[NROWS_MAX * STRIDE_];
    __shared__ float tile1[NROWS_MAX * STRIDE_];

    const int WCHUNKS = W_ / TPB;            // 2
    int bid = blockIdx.x;
    const int wchunk = bid % WCHUNKS;
    bid /= WCHUNKS;
    const int h = bid % H_;
    const int b = bid / H_;
    const int W0 = wchunk * TPB;
    const int w = W0 + threadIdx.x;
    const int tid = threadIdx.x;

    // ---- flow / weights / indices (once) ----
    const unsigned foff = (unsigned)b * (2u * PLANE_) + (unsigned)h * W_ + w;
    const float u = __ldg(flow + foff);
    const float v = __ldg(flow + foff + PLANE_);

    float fx = (float)w + u;
    float fy = (float)h + v;
    fx = fminf(fmaxf(fx, 0.0f), (float)(W_ - 1));
    fy = fminf(fmaxf(fy, 0.0f), (float)(H_ - 1));
    const int x0 = min((int)fx, W_ - 2);
    const int y0 = min((int)fy, H_ - 2);
    const float wx = fx - (float)x0;
    const float wy = fy - (float)y0;

    const float w00 = (1.0f - wy) * (1.0f - wx);
    const float w01 = (1.0f - wy) * wx;
    const float w10 = wy * (1.0f - wx);
    const float w11 = wy * wx;

    // ---- stage tile bounds ----
    const int ylo = max(0, h - M_);
    const int yhi = min(H_ - 1, h + M_ + 1);
    const int nrows = yhi - ylo + 1;                  // <= 8
    int xlo = W0 - M_;
    xlo = (xlo < 0) ? 0 : (xlo & ~3);                 // 16B aligned
    const int xhi = min(W_ - 1, W0 + TPB - 1 + M_ + 1);
    const int ncols = xhi - xlo + 1;                  // always mult of 4, <= 264
    const int ncols4 = ncols >> 2;
    const int total4 = nrows * ncols4;                // <= 528

    const bool ok = (y0 >= ylo) & (y0 + 1 <= yhi) & (x0 >= xlo) & (x0 + 1 <= xhi);
    const int sb = (y0 - ylo) * STRIDE_ + (x0 - xlo); // smem gather base

    // global offsets (fallback path + output)
    unsigned o0 = (unsigned)b * (D_ * PLANE_) + (unsigned)y0 * W_ + (unsigned)x0;
    unsigned oo = (unsigned)b * (D_ * PLANE_) + (unsigned)h * W_ + (unsigned)w;

    const float* src = img + (size_t)b * (D_ * PLANE_) + (size_t)ylo * W_ + xlo;

    for (int d = 0; d < D_; d += 2) {
        // ---- stage channels d, d+1 ----
        const float* s0 = src + (size_t)d * PLANE_;
        for (int i = tid; i < total4; i += TPB) {
            const int r = i / ncols4;
            const int c = i - r * ncols4;
            const float4* p = (const float4*)(s0 + (size_t)r * W_) + c;
            float4 a = __ldg(p);
            float4 bb = __ldg(p + (PLANE_ >> 2));
            *(float4*)&tile0[r * STRIDE_ + 4 * c] = a;
            *(float4*)&tile1[r * STRIDE_ + 4 * c] = bb;
        }
        __syncthreads();

        // ---- gather + blend, channel d ----
        float r0, r1;
        if (ok) {
            float a00 = tile0[sb];
            float a01 = tile0[sb + 1];
            float a10 = tile0[sb + STRIDE_];
            float a11 = tile0[sb + STRIDE_ + 1];
            r0 = w00 * a00;
            r0 = fmaf(w01, a01, r0);
            r0 = fmaf(w10, a10, r0);
            r0 = fmaf(w11, a11, r0);
            a00 = tile1[sb];
            a01 = tile1[sb + 1];
            a10 = tile1[sb + STRIDE_];
            a11 = tile1[sb + STRIDE_ + 1];
            r1 = w00 * a00;
            r1 = fmaf(w01, a01, r1);
            r1 = fmaf(w10, a10, r1);
            r1 = fmaf(w11, a11, r1);
        } else {
            float a00 = __ldg(img + o0);
            float a01 = __ldg(img + o0 + 1);
            float a10 = __ldg(img + o0 + W_);
            float a11 = __ldg(img + o0 + W_ + 1);
            r0 = w00 * a00;
            r0 = fmaf(w01, a01, r0);
            r0 = fmaf(w10, a10, r0);
            r0 = fmaf(w11, a11, r0);
            a00 = __ldg(img + o0 + PLANE_);
            a01 = __ldg(img + o0 + PLANE_ + 1);
            a10 = __ldg(img + o0 + PLANE_ + W_);
            a11 = __ldg(img + o0 + PLANE_ + W_ + 1);
            r1 = w00 * a00;
            r1 = fmaf(w01, a01, r1);
            r1 = fmaf(w10, a10, r1);
            r1 = fmaf(w11, a11, r1);
        }
        out[oo] = r0;
        out[oo + PLANE_] = r1;

        o0 += 2u * PLANE_;
        oo += 2u * PLANE_;
        __syncthreads();   // tiles reused next phase
    }
}

extern "C" void kernel_launch(void* const* d_in, const int* in_sizes, int n_in,
                              void* d_out, int out_size)
{
    const float* img  = (const float*)d_in[0];
    const float* flow = (const float*)d_in[1];
    float* out = (float*)d_out;

    dim3 grid(B_ * H_ * (W_ / TPB));
    dim3 block(TPB);
    resample2d_kernel<<<grid, block>>>(img, flow, out);
}